// round 1
// baseline (speedup 1.0000x reference)
#include <cuda_runtime.h>
#include <cstdint>

// StratifiedRaysampler:
//   z_j = 0.1 + j * (5.9/127),  j in [0,128)
//   points[i,j,c]  = z_j * directions[i,c] / directions[i,2]
//   lengths[i,j,0] = z_j
// d_out layout: [points (N_RAYS*128*3 f32)] ++ [lengths (N_RAYS*128 f32)]

#define N_PTS 128
#define MIN_DEPTH 0.1f
#define Z_STEP (5.9f / 127.0f)

// ---------------- points kernel: one thread = one float4 (4 consecutive floats of one ray)
__global__ void __launch_bounds__(256) points_kernel(const float* __restrict__ dirs,
                                                     float* __restrict__ out,
                                                     int n_rays) {
    // total float4s = n_rays * 96
    unsigned t = blockIdx.x * blockDim.x + threadIdx.x;
    unsigned ray = t / 96u;
    unsigned q   = t - ray * 96u;     // which float4 within the ray [0,96)
    if (ray >= (unsigned)n_rays) return;

    float d0 = __ldg(&dirs[ray * 3 + 0]);
    float d1 = __ldg(&dirs[ray * 3 + 1]);
    float d2 = __ldg(&dirs[ray * 3 + 2]);
    float inv = 1.0f / d2;
    float s[3];
    s[0] = d0 * inv;
    s[1] = d1 * inv;
    s[2] = 1.0f;          // d2/d2

    unsigned e0 = q * 4u;             // element index within ray [0,384)
    float v[4];
#pragma unroll
    for (int k = 0; k < 4; ++k) {
        unsigned e = e0 + k;
        unsigned j = e / 3u;          // point index
        unsigned c = e - j * 3u;      // coordinate
        float z = MIN_DEPTH + (float)j * Z_STEP;
        v[k] = z * s[c];
    }
    float4 val = make_float4(v[0], v[1], v[2], v[3]);
    __stcs(reinterpret_cast<float4*>(out + (size_t)ray * 384u + e0), val);
}

// ---------------- lengths kernel: pure broadcast tile of 128 z-values per ray
__global__ void __launch_bounds__(256) lengths_kernel(float* __restrict__ out,
                                                      unsigned total_f4) {
    unsigned t = blockIdx.x * blockDim.x + threadIdx.x;
    if (t >= total_f4) return;
    unsigned jbase = (t & 31u) * 4u;  // 32 float4s per ray, j = jbase..jbase+3
    float4 val;
    val.x = MIN_DEPTH + (float)(jbase + 0u) * Z_STEP;
    val.y = MIN_DEPTH + (float)(jbase + 1u) * Z_STEP;
    val.z = MIN_DEPTH + (float)(jbase + 2u) * Z_STEP;
    val.w = MIN_DEPTH + (float)(jbase + 3u) * Z_STEP;
    __stcs(reinterpret_cast<float4*>(out) + t, val);
}

extern "C" void kernel_launch(void* const* d_in, const int* in_sizes, int n_in,
                              void* d_out, int out_size) {
    // inputs: [0] origins (unused), [1] directions
    const float* dirs = (const float*)d_in[1];
    float* out = (float*)d_out;

    int n_rays = in_sizes[1] / 3;                 // 262144
    size_t points_elems = (size_t)n_rays * N_PTS * 3;   // 100663296
    float* lengths_out = out + points_elems;

    // points: n_rays * 96 float4-threads
    {
        unsigned total = (unsigned)n_rays * 96u;
        unsigned threads = 256;
        unsigned blocks = (total + threads - 1) / threads;
        points_kernel<<<blocks, threads>>>(dirs, out, n_rays);
    }
    // lengths: n_rays * 32 float4-threads
    {
        unsigned total_f4 = (unsigned)n_rays * 32u;
        unsigned threads = 256;
        unsigned blocks = (total_f4 + threads - 1) / threads;
        lengths_kernel<<<blocks, threads>>>(lengths_out, total_f4);
    }
}

// round 2
// speedup vs baseline: 1.2838x; 1.2838x over previous
#include <cuda_runtime.h>
#include <cstdint>

// StratifiedRaysampler (fused):
//   z_j = 0.1 + j * (5.9/127),  j in [0,128)
//   points[i,j,c]  = z_j * directions[i,c] / directions[i,2]
//   lengths[i,j,0] = z_j
// d_out layout: [points (N_RAYS*128*3 f32)] ++ [lengths (N_RAYS*128 f32)]
//
// One warp per ray. Lane l writes:
//   points:  float4 slots {l, 32+l, 64+l} of the ray's 96 float4s (3x STG.128, coalesced)
//   lengths: float4 slot l of the ray's 32 float4s              (1x STG.128, coalesced)

#define N_PTS 128
#define MIN_DEPTH 0.1f
#define Z_STEP (5.9f / 127.0f)

__global__ void __launch_bounds__(256) fused_raysampler_kernel(
    const float* __restrict__ dirs,
    float* __restrict__ points_out,
    float* __restrict__ lengths_out,
    unsigned n_rays)
{
    unsigned gtid = blockIdx.x * blockDim.x + threadIdx.x;
    unsigned ray  = gtid >> 5;
    unsigned lane = gtid & 31u;
    if (ray >= n_rays) return;

    // Warp-uniform loads (L1 broadcast across the warp)
    float d0 = __ldg(&dirs[ray * 3u + 0u]);
    float d1 = __ldg(&dirs[ray * 3u + 1u]);
    float d2 = __ldg(&dirs[ray * 3u + 2u]);
    float inv = 1.0f / d2;
    float s0 = d0 * inv;
    float s1 = d1 * inv;
    // s2 = d2/d2 = 1.0f

    float4* pbase = reinterpret_cast<float4*>(points_out + (size_t)ray * 384u);

#pragma unroll
    for (unsigned k = 0; k < 3; ++k) {
        unsigned e0 = 128u * k + 4u * lane;   // element index within ray [0,384)
        unsigned j  = e0 / 3u;                // single strength-reduced div per float4
        unsigned c  = e0 - 3u * j;
        float v[4];
#pragma unroll
        for (int m = 0; m < 4; ++m) {
            float z = __fmaf_rn((float)j, Z_STEP, MIN_DEPTH);
            float s = (c == 0u) ? s0 : ((c == 1u) ? s1 : 1.0f);
            v[m] = z * s;
            if (++c == 3u) { c = 0u; ++j; }
        }
        __stcs(pbase + 32u * k + lane, make_float4(v[0], v[1], v[2], v[3]));
    }

    // lengths: lane l -> z values [4l, 4l+3]
    {
        float jb = (float)(4u * lane);
        float4 lv;
        lv.x = __fmaf_rn(jb + 0.0f, Z_STEP, MIN_DEPTH);
        lv.y = __fmaf_rn(jb + 1.0f, Z_STEP, MIN_DEPTH);
        lv.z = __fmaf_rn(jb + 2.0f, Z_STEP, MIN_DEPTH);
        lv.w = __fmaf_rn(jb + 3.0f, Z_STEP, MIN_DEPTH);
        __stcs(reinterpret_cast<float4*>(lengths_out) + (size_t)ray * 32u + lane, lv);
    }
}

extern "C" void kernel_launch(void* const* d_in, const int* in_sizes, int n_in,
                              void* d_out, int out_size) {
    // inputs: [0] origins (unused), [1] directions
    const float* dirs = (const float*)d_in[1];
    float* out = (float*)d_out;

    unsigned n_rays = (unsigned)(in_sizes[1] / 3);            // 262144
    size_t points_elems = (size_t)n_rays * N_PTS * 3;         // 100663296
    float* lengths_out = out + points_elems;

    unsigned threads = 256;                                   // 8 warps = 8 rays per block
    unsigned blocks = (n_rays * 32u + threads - 1) / threads; // 32768
    fused_raysampler_kernel<<<blocks, threads>>>(dirs, out, lengths_out, n_rays);
}